// round 16
// baseline (speedup 1.0000x reference)
#include <cuda_runtime.h>
#include <cuda_bf16.h>
#include <cstdint>

typedef unsigned int u32;

#define NJ        33
#define FD        64
#define B_TOTAL   32768
#define M_TOTAL   (B_TOTAL*NJ)        // 1081344
#define TILE_M    64
#define NTILES    (M_TOTAL/TILE_M)    // 16896
#define GRID_MAIN 148
#define NTHREADS  384                 // 8 consumer warps + 4 producer warps

#define RS_BF     72                  // bf16 elems per row (144B row pitch)
#define ROW_BYTES (RS_BF*2)           // 144
#define AH_BYTES  (TILE_M*ROW_BYTES)  // 9216 per (agg or h) tile
#define BUF_BYTES (2*AH_BYTES)        // 18432 per buffer

// single fp32 staging buffer (cp.async): 3 batches = 99 rows, 272B pitch
#define STAGE_OFF   (2*BUF_BYTES)     // 36864
#define STAGE_PITCH 272               // 68 floats (17 granules -> conflict-free LDS)
#define STAGE_ROWS  99
#define STAGE_CHUNKS (STAGE_ROWS*16)  // 1584 16B chunks
#define STAGE_BYTES (STAGE_ROWS*STAGE_PITCH)   // 26928
#define SMEM_BYTES  (STAGE_OFF + STAGE_BYTES)  // 63792

// ---------------- neighbor tables (self first) ----------------
__constant__ int c_nbr[NJ][4] = {
    {0,0,0,0},{1,0,0,0},{2,0,0,0},{3,0,0,0},{4,0,0,0},{5,0,0,0},{6,0,0,0},
    {7,0,0,0},{8,0,0,0},{9,0,0,0},{10,0,0,0},
    {11,12,23,13},{12,11,24,14},{13,11,15,0},{14,12,16,0},{15,13,0,0},{16,14,0,0},
    {17,0,0,0},{18,0,0,0},{19,0,0,0},{20,0,0,0},{21,0,0,0},{22,0,0,0},
    {23,11,24,25},{24,12,23,26},{25,23,27,0},{26,24,28,0},{27,25,0,0},{28,26,0,0},
    {29,0,0,0},{30,0,0,0},{31,0,0,0},{32,0,0,0}
};
__constant__ int c_cnt[NJ] = {1,1,1,1,1,1,1,1,1,1,1, 4,4,3,3,2,2, 1,1,1,1,1,1,
                              4,4,3,3,2,2, 1,1,1,1};
__constant__ float c_invcnt[NJ] = {1.f,1.f,1.f,1.f,1.f,1.f,1.f,1.f,1.f,1.f,1.f,
                                   0.25f,0.25f,1.f/3.f,1.f/3.f,0.5f,0.5f,
                                   1.f,1.f,1.f,1.f,1.f,1.f,
                                   0.25f,0.25f,1.f/3.f,1.f/3.f,0.5f,0.5f,
                                   1.f,1.f,1.f,1.f};

// register-resident bf16 weight fragments, written by prep kernel (R8 layout).
__device__ __align__(16) u32 g_W[96*128];       // 12288 u32 = 48KB
__device__ float g_bias[256];                   // R | Z | IN | HN

// ---------------- helpers ----------------
__device__ __forceinline__ u32 smem_u32(const void* p) {
    u32 a;
    asm("{ .reg .u64 t; cvta.to.shared.u64 t, %1; cvt.u32.u64 %0, t; }" : "=r"(a) : "l"(p));
    return a;
}
__device__ __forceinline__ u32 bf2(float lo, float hi) {
    u32 r;
    asm("cvt.rn.bf16x2.f32 %0, %1, %2;" : "=r"(r) : "f"(hi), "f"(lo));
    return r;
}
__device__ __forceinline__ float tanh_ap(float x) {
    float y; asm("tanh.approx.f32 %0, %1;" : "=f"(y) : "f"(x)); return y;
}
__device__ __forceinline__ float sigm(float x) { return 0.5f * tanh_ap(0.5f * x) + 0.5f; }
__device__ __forceinline__ void mma16(float c[4], const u32 a[4], u32 b0, u32 b1) {
    asm volatile("mma.sync.aligned.m16n8k16.row.col.f32.bf16.bf16.f32 "
                 "{%0,%1,%2,%3}, {%4,%5,%6,%7}, {%8,%9}, {%0,%1,%2,%3};"
                 : "+f"(c[0]), "+f"(c[1]), "+f"(c[2]), "+f"(c[3])
                 : "r"(a[0]), "r"(a[1]), "r"(a[2]), "r"(a[3]), "r"(b0), "r"(b1));
}
__device__ __forceinline__ void ldsm4(u32 r[4], u32 addr) {
    asm volatile("ldmatrix.sync.aligned.m8n8.x4.shared.b16 {%0,%1,%2,%3}, [%4];"
                 : "=r"(r[0]), "=r"(r[1]), "=r"(r[2]), "=r"(r[3]) : "r"(addr));
}
__device__ __forceinline__ void cpa16(u32 dst, const void* src) {
    asm volatile("cp.async.cg.shared.global [%0], [%1], 16;" :: "r"(dst), "l"(src));
}
#define CP_COMMIT() asm volatile("cp.async.commit_group;" ::: "memory")
#define CP_WAIT0()  asm volatile("cp.async.wait_group 0;" ::: "memory")
#define BAR_SYNC(id)   asm volatile("bar.sync %0, %1;"   :: "r"(id), "r"(NTHREADS) : "memory")
#define BAR_ARRIVE(id) asm volatile("bar.arrive %0, %1;" :: "r"(id), "r"(NTHREADS) : "memory")
#define BAR_PROD()     asm volatile("bar.sync 5, 128;" ::: "memory")

// ---------------- prep: fold linear chain into bf16 fragment layout (R8) ----------------
__global__ void prep_kernel(const float* __restrict__ msg_w, const float* __restrict__ msg_b,
                            const float* __restrict__ w_ih, const float* __restrict__ w_hh,
                            const float* __restrict__ b_ih, const float* __restrict__ b_hh) {
    int t = blockIdx.x * blockDim.x + threadIdx.x;
    if (t < 96*128) {
        int e    = t & 3;
        int lane = (t >> 2) & 31;
        int blk  = t >> 7;            // 0..95
        int q    = blk % 3;
        int kswd = blk / 3;
        int ks   = kswd & 3;
        int wd   = kswd >> 2;
        int r    = e & 1;
        bool isH = (e >= 2);
        int gatebase = q * 64;        // 0=R, 64=Z, 128=I/HN
        int n  = gatebase + wd*8 + (lane >> 2);
        int k0 = ks*16 + (lane & 3)*2 + r*8;
        float v0, v1;
        if (!isH) {
            float s0 = 0.f, s1 = 0.f;
            #pragma unroll 8
            for (int f = 0; f < FD; f++) {
                float wi = w_ih[n*FD + f];
                s0 += msg_w[f*FD + k0]     * wi;
                s1 += msg_w[f*FD + k0 + 1] * wi;
            }
            v0 = s0; v1 = s1;
        } else {
            v0 = w_hh[n*FD + k0];
            v1 = w_hh[n*FD + k0 + 1];
        }
        g_W[t] = bf2(v0, v1);
    }
    if (t < 192) {
        float s = 0.f;
        #pragma unroll 8
        for (int f = 0; f < FD; f++) s += msg_b[f] * w_ih[t*FD + f];
        float bA = s + b_ih[t];
        if (t < 128)      g_bias[t] = bA + b_hh[t];
        else            { g_bias[t] = bA; g_bias[t + 64] = b_hh[t]; }
    }
}

// ---------------- main persistent warp-specialized kernel ----------------
__global__ void __launch_bounds__(NTHREADS, 1)
skeleton_gnn_stg(const float* __restrict__ feats,
                 const float* __restrict__ vis,
                 float* __restrict__ out)
{
    extern __shared__ char sm[];
    const int tid = threadIdx.x;

    if (tid >= 256) {
        // ===== PRODUCER (warps 8..11): phase A cp.async stage, phase B smem gather =====
        const int l    = tid - 256;            // 0..127
        const int pw   = l >> 5;               // producer warp 0..3
        const int lane = l & 31;
        const int row  = pw*16 + (lane & 15);  // 0..63
        const int kc0  = (lane >> 4) * 8;      // first float4 chunk of this half-row
        const u32 sbase = smem_u32(sm);
        const u32 stg_u = sbase + STAGE_OFF;
        const float* stg = (const float*)(sm + STAGE_OFF);

        int iter = 0;
        for (int t = blockIdx.x; t < NTILES; t += GRID_MAIN, ++iter) {
            const int p = iter & 1;
            // all producers finished reading the stage buffer (prev iter) before overwrite
            if (iter > 0) BAR_PROD();

            // ---- phase A: coalesced bulk stage of 3 covering batches ----
            const int b_lo = (t*TILE_M) / 33;
            {
                const char* src_base = (const char*)feats + (size_t)b_lo * (33*256);
                long max_bytes = ((long)M_TOTAL - (long)b_lo*33) * 256;
                #pragma unroll
                for (int i = 0; i < 13; i++) {
                    int idx = l + i*128;
                    if (idx < STAGE_CHUNKS) {
                        int rs = idx >> 4, c = idx & 15;
                        long boff = (long)idx * 16;
                        const char* src = (boff < max_bytes) ? (src_base + boff)
                                                             : (const char*)feats;
                        cpa16(stg_u + (u32)(rs*STAGE_PITCH + c*16), src);
                    }
                }
            }
            CP_COMMIT();
            CP_WAIT0();
            BAR_PROD();                       // stage visible to all producer threads

            // ---- wait for consumers to release A/H buffer p ----
            if (iter >= 2) BAR_SYNC(3 + p);
            char* As = sm + p*BUF_BYTES;
            char* Ah = As + AH_BYTES;

            // ---- phase B: gather from staged fp32 (identical arithmetic to R15) ----
            int gr = t*TILE_M + row;
            int b = (int)((u32)gr / 33u);
            int j = gr - b*33;
            const int rbase = (b - b_lo)*33;
            const float4* srow = (const float4*)(stg + (size_t)(rbase + j)*68);

            float w0 = __ldg(vis + b*NJ + j);
            float ic = c_invcnt[j];
            int cnt = c_cnt[j];
            int n1 = c_nbr[j][1], n2 = c_nbr[j][2], n3 = c_nbr[j][3];
            float wv1 = 0.f, wv2 = 0.f, wv3 = 0.f;
            if (cnt > 1) wv1 = __ldg(vis + b*NJ + n1);
            if (cnt > 2) wv2 = __ldg(vis + b*NJ + n2);
            if (cnt > 3) wv3 = __ldg(vis + b*NJ + n3);
            const float4* nr1 = (const float4*)(stg + (size_t)(rbase + n1)*68);
            const float4* nr2 = (const float4*)(stg + (size_t)(rbase + n2)*68);
            const float4* nr3 = (const float4*)(stg + (size_t)(rbase + n3)*68);

            uint4* hp = (uint4*)(Ah + row*ROW_BYTES);
            uint4* ap = (uint4*)(As + row*ROW_BYTES);
            #pragma unroll
            for (int c4 = kc0; c4 < kc0 + 8; c4 += 2) {
                float4 s0 = srow[c4], s1 = srow[c4+1];
                hp[c4 >> 1] = make_uint4(bf2(s0.x, s0.y), bf2(s0.z, s0.w),
                                         bf2(s1.x, s1.y), bf2(s1.z, s1.w));
                float a[8];
                a[0]=w0*s0.x; a[1]=w0*s0.y; a[2]=w0*s0.z; a[3]=w0*s0.w;
                a[4]=w0*s1.x; a[5]=w0*s1.y; a[6]=w0*s1.z; a[7]=w0*s1.w;
                if (cnt > 1) {
                    float4 v0 = nr1[c4], v1 = nr1[c4+1];
                    a[0]+=wv1*v0.x; a[1]+=wv1*v0.y; a[2]+=wv1*v0.z; a[3]+=wv1*v0.w;
                    a[4]+=wv1*v1.x; a[5]+=wv1*v1.y; a[6]+=wv1*v1.z; a[7]+=wv1*v1.w;
                }
                if (cnt > 2) {
                    float4 v0 = nr2[c4], v1 = nr2[c4+1];
                    a[0]+=wv2*v0.x; a[1]+=wv2*v0.y; a[2]+=wv2*v0.z; a[3]+=wv2*v0.w;
                    a[4]+=wv2*v1.x; a[5]+=wv2*v1.y; a[6]+=wv2*v1.z; a[7]+=wv2*v1.w;
                }
                if (cnt > 3) {
                    float4 v0 = nr3[c4], v1 = nr3[c4+1];
                    a[0]+=wv3*v0.x; a[1]+=wv3*v0.y; a[2]+=wv3*v0.z; a[3]+=wv3*v0.w;
                    a[4]+=wv3*v1.x; a[5]+=wv3*v1.y; a[6]+=wv3*v1.z; a[7]+=wv3*v1.w;
                }
                ap[c4 >> 1] = make_uint4(bf2(a[0]*ic, a[1]*ic), bf2(a[2]*ic, a[3]*ic),
                                         bf2(a[4]*ic, a[5]*ic), bf2(a[6]*ic, a[7]*ic));
            }
            __threadfence_block();
            BAR_ARRIVE(1 + p);
        }
    } else {
        // ================= CONSUMER (warps 0..7): R8/R15 layout, unchanged =================
        const int wd   = tid >> 5;              // d-slice: cols wd*8 .. wd*8+7
        const int lane = tid & 31;
        const int g    = lane >> 2;
        const int tig  = lane & 3;

        // --- tile-invariant bf16 weight fragments (48 u32/lane) ---
        u32 wr[4][12];
        {
            const uint4* gw4 = (const uint4*)g_W;
            #pragma unroll
            for (int ks = 0; ks < 4; ks++)
                #pragma unroll
                for (int q = 0; q < 3; q++) {
                    uint4 v = gw4[((wd*4 + ks)*3 + q)*32 + lane];
                    wr[ks][q*4+0] = v.x; wr[ks][q*4+1] = v.y;
                    wr[ks][q*4+2] = v.z; wr[ks][q*4+3] = v.w;
                }
        }
        // --- biases for this lane's two columns ---
        const int d0 = wd*8 + 2*tig;
        float bR0, bR1, bZ0, bZ1, bI0, bI1, bH0, bH1;
        {
            float2 v;
            v = *(const float2*)(g_bias + d0);        bR0 = v.x; bR1 = v.y;
            v = *(const float2*)(g_bias + 64 + d0);   bZ0 = v.x; bZ1 = v.y;
            v = *(const float2*)(g_bias + 128 + d0);  bI0 = v.x; bI1 = v.y;
            v = *(const float2*)(g_bias + 192 + d0);  bH0 = v.x; bH1 = v.y;
        }

        // ldmatrix per-lane byte offset within a buffer (mb=0, ks=0)
        const int mat  = lane >> 3;
        const int arow = (lane & 7) + ((mat & 1) << 3);
        const u32 aoff = (u32)(arow*ROW_BYTES + ((mat >> 1) << 4));
        const u32 sbase = smem_u32(sm);

        int iter = 0;
        for (int t = blockIdx.x; t < NTILES; t += GRID_MAIN, ++iter) {
            const int p = iter & 1;
            BAR_SYNC(1 + p);
            const u32 abase = sbase + (u32)(p*BUF_BYTES) + aoff;

            float accR[4][4], accZ[4][4], accI[4][4], accH[4][4];
            #pragma unroll
            for (int mb = 0; mb < 4; mb++) {
                accR[mb][0]=bR0; accR[mb][1]=bR1; accR[mb][2]=bR0; accR[mb][3]=bR1;
                accZ[mb][0]=bZ0; accZ[mb][1]=bZ1; accZ[mb][2]=bZ0; accZ[mb][3]=bZ1;
                accI[mb][0]=bI0; accI[mb][1]=bI1; accI[mb][2]=bI0; accI[mb][3]=bI1;
                accH[mb][0]=bH0; accH[mb][1]=bH1; accH[mb][2]=bH0; accH[mb][3]=bH1;
            }

            #pragma unroll
            for (int ks = 0; ks < 4; ks++) {
                #pragma unroll
                for (int mb = 0; mb < 4; mb++) {
                    u32 fa[4], fh[4];
                    const u32 ad = abase + (u32)(mb*16*ROW_BYTES + ks*32);
                    ldsm4(fa, ad);
                    ldsm4(fh, ad + AH_BYTES);
                    mma16(accR[mb], fa, wr[ks][0],  wr[ks][1]);
                    mma16(accR[mb], fh, wr[ks][2],  wr[ks][3]);
                    mma16(accZ[mb], fa, wr[ks][4],  wr[ks][5]);
                    mma16(accZ[mb], fh, wr[ks][6],  wr[ks][7]);
                    mma16(accI[mb], fa, wr[ks][8],  wr[ks][9]);
                    mma16(accH[mb], fh, wr[ks][10], wr[ks][11]);
                }
            }
            BAR_ARRIVE(3 + p);

            // gates + direct store (h re-read exact fp32 from gmem, L2-hot)
            const int gr0 = t * TILE_M;
            #pragma unroll
            for (int mb = 0; mb < 4; mb++) {
                const int r0 = gr0 + mb*16 + g;
                const int r1 = r0 + 8;
                float2 h0 = *(const float2*)(feats + (size_t)r0*FD + d0);
                float2 h1 = *(const float2*)(feats + (size_t)r1*FD + d0);
                float2 o0, o1;
                {
                    float r = sigm(accR[mb][0]), z = sigm(accZ[mb][0]);
                    float n = tanh_ap(accI[mb][0] + r*accH[mb][0]);
                    o0.x = (1.0f - z)*n + z*h0.x;
                }
                {
                    float r = sigm(accR[mb][1]), z = sigm(accZ[mb][1]);
                    float n = tanh_ap(accI[mb][1] + r*accH[mb][1]);
                    o0.y = (1.0f - z)*n + z*h0.y;
                }
                {
                    float r = sigm(accR[mb][2]), z = sigm(accZ[mb][2]);
                    float n = tanh_ap(accI[mb][2] + r*accH[mb][2]);
                    o1.x = (1.0f - z)*n + z*h1.x;
                }
                {
                    float r = sigm(accR[mb][3]), z = sigm(accZ[mb][3]);
                    float n = tanh_ap(accI[mb][3] + r*accH[mb][3]);
                    o1.y = (1.0f - z)*n + z*h1.y;
                }
                *(float2*)(out + (size_t)r0*FD + d0) = o0;
                *(float2*)(out + (size_t)r1*FD + d0) = o1;
            }
        }
    }
}

extern "C" void kernel_launch(void* const* d_in, const int* in_sizes, int n_in,
                              void* d_out, int out_size)
{
    const float* feats = (const float*)d_in[0];
    const float* vis   = (const float*)d_in[1];
    const float* msg_w = (const float*)d_in[2];
    const float* msg_b = (const float*)d_in[3];
    const float* w_ih  = (const float*)d_in[4];
    const float* w_hh  = (const float*)d_in[5];
    const float* b_ih  = (const float*)d_in[6];
    const float* b_hh  = (const float*)d_in[7];
    float* out = (float*)d_out;

    cudaFuncSetAttribute(skeleton_gnn_stg,
                         cudaFuncAttributeMaxDynamicSharedMemorySize, SMEM_BYTES);

    prep_kernel<<<24, 1024>>>(msg_w, msg_b, w_ih, w_hh, b_ih, b_hh);
    skeleton_gnn_stg<<<GRID_MAIN, NTHREADS, SMEM_BYTES>>>(feats, vis, out);
}

// round 17
// speedup vs baseline: 1.1741x; 1.1741x over previous
#include <cuda_runtime.h>
#include <cuda_bf16.h>
#include <cstdint>

typedef unsigned int u32;

#define NJ        33
#define FD        64
#define B_TOTAL   32768
#define M_TOTAL   (B_TOTAL*NJ)        // 1081344
#define TILE_M    64
#define NTILES    (M_TOTAL/TILE_M)    // 16896
#define GRID_MAIN 148
#define NTHREADS  384                 // 8 consumer warps + 4 producer warps

#define RS_BF     72                  // bf16 elems per row (144B row pitch)
#define ROW_BYTES (RS_BF*2)           // 144
#define AH_BYTES  (TILE_M*ROW_BYTES)  // 9216 per (agg or h) tile
#define BUF_BYTES (2*AH_BYTES)        // 18432 per buffer

// double-buffered fp32 staging (cp.async): 3 batches = 99 rows, 272B pitch
#define STAGE_OFF   (2*BUF_BYTES)     // 36864
#define STAGE_PITCH 272               // 68 floats (17 granules -> conflict-free LDS)
#define STAGE_ROWS  99
#define STAGE_CHUNKS (STAGE_ROWS*16)  // 1584 16B chunks
#define STAGE_BYTES (STAGE_ROWS*STAGE_PITCH)    // 26928
#define SMEM_BYTES  (STAGE_OFF + 2*STAGE_BYTES) // 90720

// ---------------- neighbor tables (self first) ----------------
__constant__ int c_nbr[NJ][4] = {
    {0,0,0,0},{1,0,0,0},{2,0,0,0},{3,0,0,0},{4,0,0,0},{5,0,0,0},{6,0,0,0},
    {7,0,0,0},{8,0,0,0},{9,0,0,0},{10,0,0,0},
    {11,12,23,13},{12,11,24,14},{13,11,15,0},{14,12,16,0},{15,13,0,0},{16,14,0,0},
    {17,0,0,0},{18,0,0,0},{19,0,0,0},{20,0,0,0},{21,0,0,0},{22,0,0,0},
    {23,11,24,25},{24,12,23,26},{25,23,27,0},{26,24,28,0},{27,25,0,0},{28,26,0,0},
    {29,0,0,0},{30,0,0,0},{31,0,0,0},{32,0,0,0}
};
__constant__ int c_cnt[NJ] = {1,1,1,1,1,1,1,1,1,1,1, 4,4,3,3,2,2, 1,1,1,1,1,1,
                              4,4,3,3,2,2, 1,1,1,1};
__constant__ float c_invcnt[NJ] = {1.f,1.f,1.f,1.f,1.f,1.f,1.f,1.f,1.f,1.f,1.f,
                                   0.25f,0.25f,1.f/3.f,1.f/3.f,0.5f,0.5f,
                                   1.f,1.f,1.f,1.f,1.f,1.f,
                                   0.25f,0.25f,1.f/3.f,1.f/3.f,0.5f,0.5f,
                                   1.f,1.f,1.f,1.f};

// register-resident bf16 weight fragments, written by prep kernel (R8 layout).
__device__ __align__(16) u32 g_W[96*128];       // 12288 u32 = 48KB
__device__ float g_bias[256];                   // R | Z | IN | HN

// ---------------- helpers ----------------
__device__ __forceinline__ u32 smem_u32(const void* p) {
    u32 a;
    asm("{ .reg .u64 t; cvta.to.shared.u64 t, %1; cvt.u32.u64 %0, t; }" : "=r"(a) : "l"(p));
    return a;
}
__device__ __forceinline__ u32 bf2(float lo, float hi) {
    u32 r;
    asm("cvt.rn.bf16x2.f32 %0, %1, %2;" : "=r"(r) : "f"(hi), "f"(lo));
    return r;
}
__device__ __forceinline__ float tanh_ap(float x) {
    float y; asm("tanh.approx.f32 %0, %1;" : "=f"(y) : "f"(x)); return y;
}
__device__ __forceinline__ float sigm(float x) { return 0.5f * tanh_ap(0.5f * x) + 0.5f; }
__device__ __forceinline__ void mma16(float c[4], const u32 a[4], u32 b0, u32 b1) {
    asm volatile("mma.sync.aligned.m16n8k16.row.col.f32.bf16.bf16.f32 "
                 "{%0,%1,%2,%3}, {%4,%5,%6,%7}, {%8,%9}, {%0,%1,%2,%3};"
                 : "+f"(c[0]), "+f"(c[1]), "+f"(c[2]), "+f"(c[3])
                 : "r"(a[0]), "r"(a[1]), "r"(a[2]), "r"(a[3]), "r"(b0), "r"(b1));
}
__device__ __forceinline__ void ldsm4(u32 r[4], u32 addr) {
    asm volatile("ldmatrix.sync.aligned.m8n8.x4.shared.b16 {%0,%1,%2,%3}, [%4];"
                 : "=r"(r[0]), "=r"(r[1]), "=r"(r[2]), "=r"(r[3]) : "r"(addr));
}
__device__ __forceinline__ void cpa16(u32 dst, const void* src) {
    asm volatile("cp.async.cg.shared.global [%0], [%1], 16;" :: "r"(dst), "l"(src));
}
#define CP_COMMIT() asm volatile("cp.async.commit_group;" ::: "memory")
#define CP_WAIT1()  asm volatile("cp.async.wait_group 1;" ::: "memory")
#define BAR_SYNC(id)   asm volatile("bar.sync %0, %1;"   :: "r"(id), "r"(NTHREADS) : "memory")
#define BAR_ARRIVE(id) asm volatile("bar.arrive %0, %1;" :: "r"(id), "r"(NTHREADS) : "memory")
#define BAR_PROD()     asm volatile("bar.sync 5, 128;" ::: "memory")

// ---------------- prep: fold linear chain into bf16 fragment layout (R8) ----------------
__global__ void prep_kernel(const float* __restrict__ msg_w, const float* __restrict__ msg_b,
                            const float* __restrict__ w_ih, const float* __restrict__ w_hh,
                            const float* __restrict__ b_ih, const float* __restrict__ b_hh) {
    int t = blockIdx.x * blockDim.x + threadIdx.x;
    if (t < 96*128) {
        int e    = t & 3;
        int lane = (t >> 2) & 31;
        int blk  = t >> 7;            // 0..95
        int q    = blk % 3;
        int kswd = blk / 3;
        int ks   = kswd & 3;
        int wd   = kswd >> 2;
        int r    = e & 1;
        bool isH = (e >= 2);
        int gatebase = q * 64;        // 0=R, 64=Z, 128=I/HN
        int n  = gatebase + wd*8 + (lane >> 2);
        int k0 = ks*16 + (lane & 3)*2 + r*8;
        float v0, v1;
        if (!isH) {
            float s0 = 0.f, s1 = 0.f;
            #pragma unroll 8
            for (int f = 0; f < FD; f++) {
                float wi = w_ih[n*FD + f];
                s0 += msg_w[f*FD + k0]     * wi;
                s1 += msg_w[f*FD + k0 + 1] * wi;
            }
            v0 = s0; v1 = s1;
        } else {
            v0 = w_hh[n*FD + k0];
            v1 = w_hh[n*FD + k0 + 1];
        }
        g_W[t] = bf2(v0, v1);
    }
    if (t < 192) {
        float s = 0.f;
        #pragma unroll 8
        for (int f = 0; f < FD; f++) s += msg_b[f] * w_ih[t*FD + f];
        float bA = s + b_ih[t];
        if (t < 128)      g_bias[t] = bA + b_hh[t];
        else            { g_bias[t] = bA; g_bias[t + 64] = b_hh[t]; }
    }
}

// issue cp.async staging of the 3 covering batches of tile t
__device__ __forceinline__ void stage_issue(const float* __restrict__ feats,
                                            int l, int t, u32 sdst) {
    int b_lo = (t*TILE_M) / 33;
    const char* src_base = (const char*)feats + (size_t)b_lo * (33*256);
    long max_bytes = ((long)M_TOTAL - (long)b_lo*33) * 256;
    #pragma unroll
    for (int i = 0; i < 13; i++) {
        int idx = l + i*128;
        if (idx < STAGE_CHUNKS) {
            int rs = idx >> 4, c = idx & 15;
            long boff = (long)idx * 16;
            const char* src = (boff < max_bytes) ? (src_base + boff) : (const char*)feats;
            cpa16(sdst + (u32)(rs*STAGE_PITCH + c*16), src);
        }
    }
}

// ---------------- main persistent warp-specialized kernel ----------------
__global__ void __launch_bounds__(NTHREADS, 1)
skeleton_gnn_stg2(const float* __restrict__ feats,
                  const float* __restrict__ vis,
                  float* __restrict__ out)
{
    extern __shared__ char sm[];
    const int tid = threadIdx.x;

    if (tid >= 256) {
        // ===== PRODUCER (warps 8..11): double-buffered stage + half-row smem gather =====
        const int l    = tid - 256;            // 0..127
        const int pw   = l >> 5;               // producer warp 0..3
        const int lane = l & 31;
        const int row  = pw*16 + (lane & 15);  // 0..63
        const int kc0  = (lane >> 4) * 8;      // first float4 chunk of this half-row
        const u32 sbase = smem_u32(sm);
        const u32 stg_u = sbase + STAGE_OFF;

        // prologue: stage first tile into buffer 0
        stage_issue(feats, l, blockIdx.x, stg_u);
        CP_COMMIT();

        int iter = 0;
        for (int t = blockIdx.x; t < NTILES; t += GRID_MAIN, ++iter) {
            const int p  = iter & 1;

            // all producers finished reading stage[(iter-1)&1] (== stage[(iter+1)&1])
            BAR_PROD();

            // issue next tile's staging into the other buffer (empty group ok at tail)
            int tn = t + GRID_MAIN;
            if (tn < NTILES)
                stage_issue(feats, l, tn, stg_u + (u32)(((iter+1)&1)*STAGE_BYTES));
            CP_COMMIT();
            CP_WAIT1();                        // current tile's stage (issued last iter) done
            BAR_PROD();                        // visibility across producer warps

            // wait for consumers to release A/H buffer p
            if (iter >= 2) BAR_SYNC(3 + p);
            char* As = sm + p*BUF_BYTES;
            char* Ah = As + AH_BYTES;

            // gather from staged fp32 (identical arithmetic to R15)
            const int b_lo = (t*TILE_M) / 33;
            const float* stg = (const float*)(sm + STAGE_OFF + (iter&1)*STAGE_BYTES);

            int gr = t*TILE_M + row;
            int b = (int)((u32)gr / 33u);
            int j = gr - b*33;
            const int rbase = (b - b_lo)*33;
            const float4* srow = (const float4*)(stg + (size_t)(rbase + j)*68);

            float w0 = __ldg(vis + b*NJ + j);
            float ic = c_invcnt[j];
            int cnt = c_cnt[j];
            int n1 = c_nbr[j][1], n2 = c_nbr[j][2], n3 = c_nbr[j][3];
            float wv1 = 0.f, wv2 = 0.f, wv3 = 0.f;
            if (cnt > 1) wv1 = __ldg(vis + b*NJ + n1);
            if (cnt > 2) wv2 = __ldg(vis + b*NJ + n2);
            if (cnt > 3) wv3 = __ldg(vis + b*NJ + n3);
            const float4* nr1 = (const float4*)(stg + (size_t)(rbase + n1)*68);
            const float4* nr2 = (const float4*)(stg + (size_t)(rbase + n2)*68);
            const float4* nr3 = (const float4*)(stg + (size_t)(rbase + n3)*68);

            uint4* hp = (uint4*)(Ah + row*ROW_BYTES);
            uint4* ap = (uint4*)(As + row*ROW_BYTES);
            #pragma unroll
            for (int c4 = kc0; c4 < kc0 + 8; c4 += 2) {
                float4 s0 = srow[c4], s1 = srow[c4+1];
                hp[c4 >> 1] = make_uint4(bf2(s0.x, s0.y), bf2(s0.z, s0.w),
                                         bf2(s1.x, s1.y), bf2(s1.z, s1.w));
                float a[8];
                a[0]=w0*s0.x; a[1]=w0*s0.y; a[2]=w0*s0.z; a[3]=w0*s0.w;
                a[4]=w0*s1.x; a[5]=w0*s1.y; a[6]=w0*s1.z; a[7]=w0*s1.w;
                if (cnt > 1) {
                    float4 v0 = nr1[c4], v1 = nr1[c4+1];
                    a[0]+=wv1*v0.x; a[1]+=wv1*v0.y; a[2]+=wv1*v0.z; a[3]+=wv1*v0.w;
                    a[4]+=wv1*v1.x; a[5]+=wv1*v1.y; a[6]+=wv1*v1.z; a[7]+=wv1*v1.w;
                }
                if (cnt > 2) {
                    float4 v0 = nr2[c4], v1 = nr2[c4+1];
                    a[0]+=wv2*v0.x; a[1]+=wv2*v0.y; a[2]+=wv2*v0.z; a[3]+=wv2*v0.w;
                    a[4]+=wv2*v1.x; a[5]+=wv2*v1.y; a[6]+=wv2*v1.z; a[7]+=wv2*v1.w;
                }
                if (cnt > 3) {
                    float4 v0 = nr3[c4], v1 = nr3[c4+1];
                    a[0]+=wv3*v0.x; a[1]+=wv3*v0.y; a[2]+=wv3*v0.z; a[3]+=wv3*v0.w;
                    a[4]+=wv3*v1.x; a[5]+=wv3*v1.y; a[6]+=wv3*v1.z; a[7]+=wv3*v1.w;
                }
                ap[c4 >> 1] = make_uint4(bf2(a[0]*ic, a[1]*ic), bf2(a[2]*ic, a[3]*ic),
                                         bf2(a[4]*ic, a[5]*ic), bf2(a[6]*ic, a[7]*ic));
            }
            __threadfence_block();
            BAR_ARRIVE(1 + p);
        }
    } else {
        // ================= CONSUMER (warps 0..7): R8/R15 layout, unchanged =================
        const int wd   = tid >> 5;              // d-slice: cols wd*8 .. wd*8+7
        const int lane = tid & 31;
        const int g    = lane >> 2;
        const int tig  = lane & 3;

        // --- tile-invariant bf16 weight fragments (48 u32/lane) ---
        u32 wr[4][12];
        {
            const uint4* gw4 = (const uint4*)g_W;
            #pragma unroll
            for (int ks = 0; ks < 4; ks++)
                #pragma unroll
                for (int q = 0; q < 3; q++) {
                    uint4 v = gw4[((wd*4 + ks)*3 + q)*32 + lane];
                    wr[ks][q*4+0] = v.x; wr[ks][q*4+1] = v.y;
                    wr[ks][q*4+2] = v.z; wr[ks][q*4+3] = v.w;
                }
        }
        // --- biases for this lane's two columns ---
        const int d0 = wd*8 + 2*tig;
        float bR0, bR1, bZ0, bZ1, bI0, bI1, bH0, bH1;
        {
            float2 v;
            v = *(const float2*)(g_bias + d0);        bR0 = v.x; bR1 = v.y;
            v = *(const float2*)(g_bias + 64 + d0);   bZ0 = v.x; bZ1 = v.y;
            v = *(const float2*)(g_bias + 128 + d0);  bI0 = v.x; bI1 = v.y;
            v = *(const float2*)(g_bias + 192 + d0);  bH0 = v.x; bH1 = v.y;
        }

        // ldmatrix per-lane byte offset within a buffer (mb=0, ks=0)
        const int mat  = lane >> 3;
        const int arow = (lane & 7) + ((mat & 1) << 3);
        const u32 aoff = (u32)(arow*ROW_BYTES + ((mat >> 1) << 4));
        const u32 sbase = smem_u32(sm);

        int iter = 0;
        for (int t = blockIdx.x; t < NTILES; t += GRID_MAIN, ++iter) {
            const int p = iter & 1;
            BAR_SYNC(1 + p);
            const u32 abase = sbase + (u32)(p*BUF_BYTES) + aoff;

            float accR[4][4], accZ[4][4], accI[4][4], accH[4][4];
            #pragma unroll
            for (int mb = 0; mb < 4; mb++) {
                accR[mb][0]=bR0; accR[mb][1]=bR1; accR[mb][2]=bR0; accR[mb][3]=bR1;
                accZ[mb][0]=bZ0; accZ[mb][1]=bZ1; accZ[mb][2]=bZ0; accZ[mb][3]=bZ1;
                accI[mb][0]=bI0; accI[mb][1]=bI1; accI[mb][2]=bI0; accI[mb][3]=bI1;
                accH[mb][0]=bH0; accH[mb][1]=bH1; accH[mb][2]=bH0; accH[mb][3]=bH1;
            }

            #pragma unroll
            for (int ks = 0; ks < 4; ks++) {
                #pragma unroll
                for (int mb = 0; mb < 4; mb++) {
                    u32 fa[4], fh[4];
                    const u32 ad = abase + (u32)(mb*16*ROW_BYTES + ks*32);
                    ldsm4(fa, ad);
                    ldsm4(fh, ad + AH_BYTES);
                    mma16(accR[mb], fa, wr[ks][0],  wr[ks][1]);
                    mma16(accR[mb], fh, wr[ks][2],  wr[ks][3]);
                    mma16(accZ[mb], fa, wr[ks][4],  wr[ks][5]);
                    mma16(accZ[mb], fh, wr[ks][6],  wr[ks][7]);
                    mma16(accI[mb], fa, wr[ks][8],  wr[ks][9]);
                    mma16(accH[mb], fh, wr[ks][10], wr[ks][11]);
                }
            }
            BAR_ARRIVE(3 + p);

            // gates + direct store (h re-read exact fp32 from gmem, L2-hot)
            const int gr0 = t * TILE_M;
            #pragma unroll
            for (int mb = 0; mb < 4; mb++) {
                const int r0 = gr0 + mb*16 + g;
                const int r1 = r0 + 8;
                float2 h0 = *(const float2*)(feats + (size_t)r0*FD + d0);
                float2 h1 = *(const float2*)(feats + (size_t)r1*FD + d0);
                float2 o0, o1;
                {
                    float r = sigm(accR[mb][0]), z = sigm(accZ[mb][0]);
                    float n = tanh_ap(accI[mb][0] + r*accH[mb][0]);
                    o0.x = (1.0f - z)*n + z*h0.x;
                }
                {
                    float r = sigm(accR[mb][1]), z = sigm(accZ[mb][1]);
                    float n = tanh_ap(accI[mb][1] + r*accH[mb][1]);
                    o0.y = (1.0f - z)*n + z*h0.y;
                }
                {
                    float r = sigm(accR[mb][2]), z = sigm(accZ[mb][2]);
                    float n = tanh_ap(accI[mb][2] + r*accH[mb][2]);
                    o1.x = (1.0f - z)*n + z*h1.x;
                }
                {
                    float r = sigm(accR[mb][3]), z = sigm(accZ[mb][3]);
                    float n = tanh_ap(accI[mb][3] + r*accH[mb][3]);
                    o1.y = (1.0f - z)*n + z*h1.y;
                }
                *(float2*)(out + (size_t)r0*FD + d0) = o0;
                *(float2*)(out + (size_t)r1*FD + d0) = o1;
            }
        }
    }
}

extern "C" void kernel_launch(void* const* d_in, const int* in_sizes, int n_in,
                              void* d_out, int out_size)
{
    const float* feats = (const float*)d_in[0];
    const float* vis   = (const float*)d_in[1];
    const float* msg_w = (const float*)d_in[2];
    const float* msg_b = (const float*)d_in[3];
    const float* w_ih  = (const float*)d_in[4];
    const float* w_hh  = (const float*)d_in[5];
    const float* b_ih  = (const float*)d_in[6];
    const float* b_hh  = (const float*)d_in[7];
    float* out = (float*)d_out;

    cudaFuncSetAttribute(skeleton_gnn_stg2,
                         cudaFuncAttributeMaxDynamicSharedMemorySize, SMEM_BYTES);

    prep_kernel<<<24, 1024>>>(msg_w, msg_b, w_ih, w_hh, b_ih, b_hh);
    skeleton_gnn_stg2<<<GRID_MAIN, NTHREADS, SMEM_BYTES>>>(feats, vis, out);
}